// round 14
// baseline (speedup 1.0000x reference)
#include <cuda_runtime.h>

typedef unsigned int u32;

#define Tt    512
#define FOUT  20
#define NBLK  128

__device__ __forceinline__ float tanha(float x) {
    float y; asm("tanh.approx.f32 %0,%1;" : "=f"(y) : "f"(x)); return y;
}
__device__ __forceinline__ float totf(float x) {
    u32 r; asm("cvt.rna.tf32.f32 %0,%1;" : "=r"(r) : "f"(x));
    return __uint_as_float(r);
}
__device__ __forceinline__ u32 tfu(float x) {
    u32 r; asm("cvt.rna.tf32.f32 %0,%1;" : "=r"(r) : "f"(x));
    return r;
}
// D = A(16x8 tf32, row) * B(8x8 tf32, col) + D   (f32 accum)
__device__ __forceinline__ void mma8(float c[4], const u32 a[4], u32 b0, u32 b1) {
    asm volatile(
        "mma.sync.aligned.m16n8k8.row.col.f32.tf32.tf32.f32 "
        "{%0,%1,%2,%3},{%4,%5,%6,%7},{%8,%9},{%0,%1,%2,%3};"
        : "+f"(c[0]), "+f"(c[1]), "+f"(c[2]), "+f"(c[3])
        : "r"(a[0]), "r"(a[1]), "r"(a[2]), "r"(a[3]), "r"(b0), "r"(b1));
}

__global__ void __launch_bounds__(256, 1)
lstm_mma_kernel(const float* __restrict__ x,
                const float* __restrict__ Wih1, const float* __restrict__ Whh1,
                const float* __restrict__ bih1, const float* __restrict__ bhh1,
                const float* __restrict__ Wih2, const float* __restrict__ Whh2,
                const float* __restrict__ bih2, const float* __restrict__ bhh2,
                const float* __restrict__ Wout, const float* __restrict__ bout,
                float* __restrict__ out)
{
    // z tiles, stride 36 for conflict-free B-fragment loads.
    // z1: rows 0..1 = x(t), 2..33 = h1, 34..39 = zero pad.  z2: 0..31 = h1(t), 32..63 = h2.
    __shared__ float z1h[40][36], z1l[40][36];
    __shared__ float z2h[64][36], z2l[64][36];

    const int tid  = threadIdx.x;
    const int w    = tid >> 5, lane = tid & 31;
    const int gid  = lane >> 2, tig = lane & 3;
    const int sBase = blockIdx.x * 32;

    for (int i = tid; i < 40 * 36; i += 256) { (&z1h[0][0])[i] = 0.f; (&z1l[0][0])[i] = 0.f; }
    for (int i = tid; i < 64 * 36; i += 256) { (&z2h[0][0])[i] = 0.f; (&z2l[0][0])[i] = 0.f; }

    // ---- gate-row indices: global row R = w*16 + gid (+8); R = 4*unit + gate ----
    const int Rlo = w * 16 + gid, Rhi = Rlo + 8;

    // weight fetchers (row-interleaved)
    auto w1v = [&](int R, int k) -> float {
        if (k >= 34) return 0.f;
        int u = R >> 2, g = R & 3;
        return (k < 2) ? Wih1[(g * 32 + u) * 2 + k] : Whh1[(g * 32 + u) * 32 + (k - 2)];
    };
    auto w2v = [&](int R, int k) -> float {
        int u = R >> 2, g = R & 3;
        return (k < 32) ? Wih2[(g * 32 + u) * 32 + k] : Whh2[(g * 32 + u) * 32 + (k - 32)];
    };

    // ---- A fragments (weights, resident in registers; hi + lo split) ----
    u32 a1h[5][4], a1l[5][4];
    #pragma unroll
    for (int kt = 0; kt < 5; kt++) {
        int rows[2] = { Rlo, Rhi };
        #pragma unroll
        for (int i = 0; i < 4; i++) {
            int r = rows[i & 1];
            int k = kt * 8 + tig + ((i >= 2) ? 4 : 0);
            float v = w1v(r, k), hi = totf(v);
            a1h[kt][i] = __float_as_uint(hi);
            a1l[kt][i] = tfu(v - hi);
        }
    }
    u32 a2h[8][4], a2l[8][4];
    #pragma unroll
    for (int kt = 0; kt < 8; kt++) {
        int rows[2] = { Rlo, Rhi };
        #pragma unroll
        for (int i = 0; i < 4; i++) {
            int r = rows[i & 1];
            int k = kt * 8 + tig + ((i >= 2) ? 4 : 0);
            float v = w2v(r, k), hi = totf(v);
            a2h[kt][i] = __float_as_uint(hi);
            a2l[kt][i] = tfu(v - hi);
        }
    }
    // head A: warp w handles (mt = w>>2, nt = w&3); rows hR = mt*16 + gid (+8), K=32
    const int oLo = (w >> 2) * 16 + gid, oHi = oLo + 8;
    u32 ahh[4][4], ahl[4][4];
    #pragma unroll
    for (int kt = 0; kt < 4; kt++) {
        int rows[2] = { oLo, oHi };
        #pragma unroll
        for (int i = 0; i < 4; i++) {
            int r = rows[i & 1];
            int k = kt * 8 + tig + ((i >= 2) ? 4 : 0);
            float v = (r < FOUT) ? Wout[r * 32 + k] : 0.f;
            float hi = totf(v);
            ahh[kt][i] = __float_as_uint(hi);
            ahl[kt][i] = tfu(v - hi);
        }
    }

    // ---- biases ----
    const int uL = Rlo >> 2, gL = Rlo & 3;
    const int uH = Rhi >> 2;   // same gate
    const float b1lo = bih1[gL * 32 + uL] + bhh1[gL * 32 + uL];
    const float b1hi = bih1[gL * 32 + uH] + bhh1[gL * 32 + uH];
    const float b2lo = bih2[gL * 32 + uL] + bhh2[gL * 32 + uL];
    const float b2hi = bih2[gL * 32 + uH] + bhh2[gL * 32 + uH];
    const float boLo = (oLo < FOUT) ? bout[oLo] : 0.f;
    const float boHi = (oHi < FOUT) ? bout[oHi] : 0.f;

    // activation constants: gate gL==2 -> tanh; else sigmoid = 0.5*tanh(0.5x)+0.5
    const float mB = (gL == 2) ? 1.f : 0.5f;
    const float kM = (gL == 2) ? 1.f : 0.5f;
    const float kA = (gL == 2) ? 0.f : 0.5f;
    const bool  mine = (gL == 1);                 // f-gate lanes own c/h
    const int   uA   = 4 * w + (gid >> 2);

    // stage x(0); prefetch x(1)  (warp 7)
    float2 xv = make_float2(0.f, 0.f);
    if (w == 7) {
        float2 x0 = ((const float2*)x)[(size_t)(sBase + lane) * Tt];
        float hx = totf(x0.x), hy = totf(x0.y);
        z1h[0][lane] = hx; z1l[0][lane] = totf(x0.x - hx);
        z1h[1][lane] = hy; z1l[1][lane] = totf(x0.y - hy);
        xv = ((const float2*)x)[(size_t)(sBase + lane) * Tt + 1];
    }
    __syncthreads();

    float c1s[16], c2s[16];
    #pragma unroll
    for (int i = 0; i < 16; i++) { c1s[i] = 0.f; c2s[i] = 0.f; }

    float acc[4][4];

    #pragma unroll 1
    for (int t = 0; t < Tt; t++) {
        // ======== phase A: L1 gates (reads z1) ========
        #pragma unroll
        for (int nt = 0; nt < 4; nt++) {
            acc[nt][0] = b1lo; acc[nt][1] = b1lo; acc[nt][2] = b1hi; acc[nt][3] = b1hi;
        }
        #pragma unroll
        for (int kt = 0; kt < 5; kt++) {
            int k0 = kt * 8 + tig;
            #pragma unroll
            for (int nt = 0; nt < 4; nt++) {
                int n = nt * 8 + gid;
                u32 bh0 = __float_as_uint(z1h[k0][n]), bh1 = __float_as_uint(z1h[k0 + 4][n]);
                u32 bl0 = __float_as_uint(z1l[k0][n]), bl1 = __float_as_uint(z1l[k0 + 4][n]);
                mma8(acc[nt], a1h[kt], bh0, bh1);
                mma8(acc[nt], a1l[kt], bh0, bh1);
                mma8(acc[nt], a1h[kt], bl0, bl1);
            }
        }
        // ---- head for t-1 (reads z2 rows 32..63 = h2(t-1)) ----
        if (t > 0) {
            float ha[4] = { boLo, boLo, boHi, boHi };
            int nt = w & 3, n = nt * 8 + gid;
            #pragma unroll
            for (int kt = 0; kt < 4; kt++) {
                int k0 = 32 + kt * 8 + tig;
                u32 bh0 = __float_as_uint(z2h[k0][n]), bh1 = __float_as_uint(z2h[k0 + 4][n]);
                u32 bl0 = __float_as_uint(z2l[k0][n]), bl1 = __float_as_uint(z2l[k0 + 4][n]);
                mma8(ha, ahh[kt], bh0, bh1);
                mma8(ha, ahl[kt], bh0, bh1);
                mma8(ha, ahh[kt], bl0, bl1);
            }
            int s0 = nt * 8 + 2 * tig;
            size_t r0 = ((size_t)(sBase + s0) * Tt + (t - 1)) * FOUT;
            size_t r1 = ((size_t)(sBase + s0 + 1) * Tt + (t - 1)) * FOUT;
            if (oLo < FOUT) { out[r0 + oLo] = ha[0]; out[r1 + oLo] = ha[1]; }
            if (oHi < FOUT) { out[r0 + oHi] = ha[2]; out[r1 + oHi] = ha[3]; }
        }
        __syncthreads();   // all z1/z2 phase-A reads complete

        // ======== L1 epilogue: h1(t) -> z1 rows 2.., z2 rows 0..31 ========
        #pragma unroll
        for (int nt = 0; nt < 4; nt++) {
            #pragma unroll
            for (int ci = 0; ci < 4; ci++) {
                float v  = fmaf(kM, tanha(mB * acc[nt][ci]), kA);
                float tp = __shfl_xor_sync(0xffffffffu, v, 8);   // gate^2 partner
                float q  = v * tp;                               // g0: sig(i)*tanh(g)
                float ig = __shfl_xor_sync(0xffffffffu, q, 4);   // g1 receives i*g
                float c  = fmaf(v, c1s[nt * 4 + ci], ig);        // g1: f*c + i*g
                c1s[nt * 4 + ci] = c;
                float h  = tp * tanha(c);                        // g1: o*tanh(c)
                if (mine) {
                    int u = uA + ((ci >= 2) ? 2 : 0);
                    int s = nt * 8 + 2 * tig + (ci & 1);
                    float hh = totf(h), hl = totf(h - hh);
                    z1h[2 + u][s] = hh; z1l[2 + u][s] = hl;
                    z2h[u][s]     = hh; z2l[u][s]     = hl;
                }
            }
        }
        // stage x(t+1); prefetch x(t+2)
        if (w == 7) {
            float hx = totf(xv.x), hy = totf(xv.y);
            z1h[0][lane] = hx; z1l[0][lane] = totf(xv.x - hx);
            z1h[1][lane] = hy; z1l[1][lane] = totf(xv.y - hy);
            if (t + 2 < Tt) xv = ((const float2*)x)[(size_t)(sBase + lane) * Tt + t + 2];
        }
        __syncthreads();   // h1(t), x(t+1) visible

        // ======== phase B: L2 gates (reads z2 rows 0..63) ========
        #pragma unroll
        for (int nt = 0; nt < 4; nt++) {
            acc[nt][0] = b2lo; acc[nt][1] = b2lo; acc[nt][2] = b2hi; acc[nt][3] = b2hi;
        }
        #pragma unroll
        for (int kt = 0; kt < 8; kt++) {
            int k0 = kt * 8 + tig;
            #pragma unroll
            for (int nt = 0; nt < 4; nt++) {
                int n = nt * 8 + gid;
                u32 bh0 = __float_as_uint(z2h[k0][n]), bh1 = __float_as_uint(z2h[k0 + 4][n]);
                u32 bl0 = __float_as_uint(z2l[k0][n]), bl1 = __float_as_uint(z2l[k0 + 4][n]);
                mma8(acc[nt], a2h[kt], bh0, bh1);
                mma8(acc[nt], a2l[kt], bh0, bh1);
                mma8(acc[nt], a2h[kt], bl0, bl1);
            }
        }
        __syncthreads();   // all reads of h2(t-1) rows complete before overwrite

        // ======== L2 epilogue: h2(t) -> z2 rows 32..63 ========
        #pragma unroll
        for (int nt = 0; nt < 4; nt++) {
            #pragma unroll
            for (int ci = 0; ci < 4; ci++) {
                float v  = fmaf(kM, tanha(mB * acc[nt][ci]), kA);
                float tp = __shfl_xor_sync(0xffffffffu, v, 8);
                float q  = v * tp;
                float ig = __shfl_xor_sync(0xffffffffu, q, 4);
                float c  = fmaf(v, c2s[nt * 4 + ci], ig);
                c2s[nt * 4 + ci] = c;
                float h  = tp * tanha(c);
                if (mine) {
                    int u = uA + ((ci >= 2) ? 2 : 0);
                    int s = nt * 8 + 2 * tig + (ci & 1);
                    float hh = totf(h), hl = totf(h - hh);
                    z2h[32 + u][s] = hh; z2l[32 + u][s] = hl;
                }
            }
        }
        __syncthreads();   // h2(t) visible for next step
    }

    // ======== final head: t = Tt-1 ========
    {
        float ha[4] = { boLo, boLo, boHi, boHi };
        int nt = w & 3, n = nt * 8 + gid;
        #pragma unroll
        for (int kt = 0; kt < 4; kt++) {
            int k0 = 32 + kt * 8 + tig;
            u32 bh0 = __float_as_uint(z2h[k0][n]), bh1 = __float_as_uint(z2h[k0 + 4][n]);
            u32 bl0 = __float_as_uint(z2l[k0][n]), bl1 = __float_as_uint(z2l[k0 + 4][n]);
            mma8(ha, ahh[kt], bh0, bh1);
            mma8(ha, ahl[kt], bh0, bh1);
            mma8(ha, ahh[kt], bl0, bl1);
        }
        int s0 = nt * 8 + 2 * tig;
        size_t r0 = ((size_t)(sBase + s0) * Tt + (Tt - 1)) * FOUT;
        size_t r1 = ((size_t)(sBase + s0 + 1) * Tt + (Tt - 1)) * FOUT;
        if (oLo < FOUT) { out[r0 + oLo] = ha[0]; out[r1 + oLo] = ha[1]; }
        if (oHi < FOUT) { out[r0 + oHi] = ha[2]; out[r1 + oHi] = ha[3]; }
    }
}

extern "C" void kernel_launch(void* const* d_in, const int* in_sizes, int n_in,
                              void* d_out, int out_size) {
    const float* x    = (const float*)d_in[0];
    const float* Wih1 = (const float*)d_in[1];
    const float* Whh1 = (const float*)d_in[2];
    const float* bih1 = (const float*)d_in[3];
    const float* bhh1 = (const float*)d_in[4];
    const float* Wih2 = (const float*)d_in[5];
    const float* Whh2 = (const float*)d_in[6];
    const float* bih2 = (const float*)d_in[7];
    const float* bhh2 = (const float*)d_in[8];
    const float* Wout = (const float*)d_in[9];
    const float* bout = (const float*)d_in[10];
    float* out = (float*)d_out;

    lstm_mma_kernel<<<NBLK, 256>>>(
        x, Wih1, Whh1, bih1, bhh1, Wih2, Whh2, bih2, bhh2, Wout, bout, out);
}

// round 15
// speedup vs baseline: 2.2660x; 2.2660x over previous
#include <cuda_runtime.h>

typedef unsigned int u32;

#define Tt    512
#define FOUT  20
#define NBLK  128

__device__ __forceinline__ float tanha(float x) {
    float y; asm("tanh.approx.f32 %0,%1;" : "=f"(y) : "f"(x)); return y;
}
__device__ __forceinline__ float totf(float x) {
    u32 r; asm("cvt.rna.tf32.f32 %0,%1;" : "=r"(r) : "f"(x));
    return __uint_as_float(r);
}
__device__ __forceinline__ u32 tfu(float x) {
    u32 r; asm("cvt.rna.tf32.f32 %0,%1;" : "=r"(r) : "f"(x));
    return r;
}
// D = A(16x8 tf32, row) * B(8x8 tf32, col) + D   (f32 accum)
__device__ __forceinline__ void mma8(float c[4], const u32 a[4], u32 b0, u32 b1) {
    asm volatile(
        "mma.sync.aligned.m16n8k8.row.col.f32.tf32.tf32.f32 "
        "{%0,%1,%2,%3},{%4,%5,%6,%7},{%8,%9},{%0,%1,%2,%3};"
        : "+f"(c[0]), "+f"(c[1]), "+f"(c[2]), "+f"(c[3])
        : "r"(a[0]), "r"(a[1]), "r"(a[2]), "r"(a[3]), "r"(b0), "r"(b1));
}

__global__ void __launch_bounds__(256, 1)
lstm_mma_kernel(const float* __restrict__ x,
                const float* __restrict__ Wih1, const float* __restrict__ Whh1,
                const float* __restrict__ bih1, const float* __restrict__ bhh1,
                const float* __restrict__ Wih2, const float* __restrict__ Whh2,
                const float* __restrict__ bih2, const float* __restrict__ bhh2,
                const float* __restrict__ Wout, const float* __restrict__ bout,
                float* __restrict__ out)
{
    // z tiles (tf32-hi only), stride 36.
    // z1: rows 0..1 = x(t), 2..33 = h1, 34..39 pad.
    // z2: rows 0..31 = h1(t); h2 double-buffered: rows 32..63 (par 0), 64..95 (par 1).
    __shared__ float z1h[40][36];
    __shared__ float z2h[96][36];

    const int tid  = threadIdx.x;
    const int w    = tid >> 5, lane = tid & 31;
    const int gid  = lane >> 2, tig = lane & 3;
    const int sBase = blockIdx.x * 32;

    for (int i = tid; i < 40 * 36; i += 256) (&z1h[0][0])[i] = 0.f;
    for (int i = tid; i < 96 * 36; i += 256) (&z2h[0][0])[i] = 0.f;

    // ---- gate-row indices: global row R = w*16 + gid (+8); R = 4*unit + gate ----
    const int Rlo = w * 16 + gid, Rhi = Rlo + 8;

    auto w1v = [&](int R, int k) -> float {
        if (k >= 34) return 0.f;
        int u = R >> 2, g = R & 3;
        return (k < 2) ? Wih1[(g * 32 + u) * 2 + k] : Whh1[(g * 32 + u) * 32 + (k - 2)];
    };
    auto w2v = [&](int R, int k) -> float {
        int u = R >> 2, g = R & 3;
        return (k < 32) ? Wih2[(g * 32 + u) * 32 + k] : Whh2[(g * 32 + u) * 32 + (k - 32)];
    };

    // ---- A fragments (weights resident in registers; hi + lo split) ----
    u32 a1h[5][4], a1l[5][4];
    #pragma unroll
    for (int kt = 0; kt < 5; kt++) {
        int rows[2] = { Rlo, Rhi };
        #pragma unroll
        for (int i = 0; i < 4; i++) {
            int r = rows[i & 1];
            int k = kt * 8 + tig + ((i >= 2) ? 4 : 0);
            float v = w1v(r, k), hi = totf(v);
            a1h[kt][i] = __float_as_uint(hi);
            a1l[kt][i] = tfu(v - hi);
        }
    }
    u32 a2h[8][4], a2l[8][4];
    #pragma unroll
    for (int kt = 0; kt < 8; kt++) {
        int rows[2] = { Rlo, Rhi };
        #pragma unroll
        for (int i = 0; i < 4; i++) {
            int r = rows[i & 1];
            int k = kt * 8 + tig + ((i >= 2) ? 4 : 0);
            float v = w2v(r, k), hi = totf(v);
            a2h[kt][i] = __float_as_uint(hi);
            a2l[kt][i] = tfu(v - hi);
        }
    }
    // head A: warp w -> (mt = w>>2, nt = w&3); rows = mt*16 + gid (+8), K=32
    const int oLo = (w >> 2) * 16 + gid, oHi = oLo + 8;
    u32 ahh[4][4], ahl[4][4];
    #pragma unroll
    for (int kt = 0; kt < 4; kt++) {
        int rows[2] = { oLo, oHi };
        #pragma unroll
        for (int i = 0; i < 4; i++) {
            int r = rows[i & 1];
            int k = kt * 8 + tig + ((i >= 2) ? 4 : 0);
            float v = (r < FOUT) ? Wout[r * 32 + k] : 0.f;
            float hi = totf(v);
            ahh[kt][i] = __float_as_uint(hi);
            ahl[kt][i] = tfu(v - hi);
        }
    }

    // ---- biases / activation constants ----
    const int uL = Rlo >> 2, gL = Rlo & 3;
    const int uH = Rhi >> 2;
    const float b1lo = bih1[gL * 32 + uL] + bhh1[gL * 32 + uL];
    const float b1hi = bih1[gL * 32 + uH] + bhh1[gL * 32 + uH];
    const float b2lo = bih2[gL * 32 + uL] + bhh2[gL * 32 + uL];
    const float b2hi = bih2[gL * 32 + uH] + bhh2[gL * 32 + uH];
    const float boLo = (oLo < FOUT) ? bout[oLo] : 0.f;
    const float boHi = (oHi < FOUT) ? bout[oHi] : 0.f;
    const float mB = (gL == 2) ? 1.f : 0.5f;
    const float kM = (gL == 2) ? 1.f : 0.5f;
    const float kA = (gL == 2) ? 0.f : 0.5f;
    const bool  mine = (gL == 1);
    const int   uA   = 4 * w + (gid >> 2);

    // stage x(0); prefetch x(1)
    float2 xv = make_float2(0.f, 0.f);
    if (w == 7) {
        float2 x0 = ((const float2*)x)[(size_t)(sBase + lane) * Tt];
        z1h[0][lane] = totf(x0.x);
        z1h[1][lane] = totf(x0.y);
        xv = ((const float2*)x)[(size_t)(sBase + lane) * Tt + 1];
    }
    __syncthreads();

    float c1s[16], c2s[16];
    #pragma unroll
    for (int i = 0; i < 16; i++) { c1s[i] = 0.f; c2s[i] = 0.f; }

    float accH[4][4], accL[4][4];

    #pragma unroll 1
    for (int t = 0; t < Tt; t++) {
        const int rb = 32 + 32 * ((t & 1) ^ 1);   // h2(t-1) buffer base
        const int wb2 = 32 + 32 * (t & 1);        // h2(t) buffer base

        // ======== head for t-1 (first: overlaps phase A) ========
        float haH[4], haL[4];
        if (t > 0) {
            haH[0] = boLo; haH[1] = boLo; haH[2] = boHi; haH[3] = boHi;
            haL[0] = 0.f;  haL[1] = 0.f;  haL[2] = 0.f;  haL[3] = 0.f;
            int nt = w & 3, n = nt * 8 + gid;
            #pragma unroll
            for (int kt = 0; kt < 4; kt++) {
                int k0 = kt * 8 + tig;
                u32 bh0 = __float_as_uint(z2h[rb + k0][n]);
                u32 bh1 = __float_as_uint(z2h[rb + k0 + 4][n]);
                mma8(haH, ahh[kt], bh0, bh1);
                mma8(haL, ahl[kt], bh0, bh1);
            }
        }

        // ======== phase A: L1 gates (reads z1) ========
        #pragma unroll
        for (int nt = 0; nt < 4; nt++) {
            accH[nt][0] = b1lo; accH[nt][1] = b1lo; accH[nt][2] = b1hi; accH[nt][3] = b1hi;
            accL[nt][0] = 0.f;  accL[nt][1] = 0.f;  accL[nt][2] = 0.f;  accL[nt][3] = 0.f;
        }
        #pragma unroll
        for (int kt = 0; kt < 5; kt++) {
            int k0 = kt * 8 + tig;
            #pragma unroll
            for (int nt = 0; nt < 4; nt++) {
                int n = nt * 8 + gid;
                u32 bh0 = __float_as_uint(z1h[k0][n]), bh1 = __float_as_uint(z1h[k0 + 4][n]);
                mma8(accH[nt], a1h[kt], bh0, bh1);
                mma8(accL[nt], a1l[kt], bh0, bh1);
            }
        }

        // head stores (mma results drained by now)
        if (t > 0) {
            int nt = w & 3;
            int s0 = nt * 8 + 2 * tig;
            size_t r0 = ((size_t)(sBase + s0) * Tt + (t - 1)) * FOUT;
            size_t r1 = ((size_t)(sBase + s0 + 1) * Tt + (t - 1)) * FOUT;
            if (oLo < FOUT) { out[r0 + oLo] = haH[0] + haL[0]; out[r1 + oLo] = haH[1] + haL[1]; }
            if (oHi < FOUT) { out[r0 + oHi] = haH[2] + haL[2]; out[r1 + oHi] = haH[3] + haL[3]; }
        }
        __syncthreads();   // phase A z1 reads + head/phase-B-prev z2 reads complete

        // ======== L1 epilogue: h1(t) -> z1 rows 2.., z2 rows 0..31 ========
        #pragma unroll
        for (int nt = 0; nt < 4; nt++) {
            #pragma unroll
            for (int ci = 0; ci < 4; ci++) {
                float pre = accH[nt][ci] + accL[nt][ci];
                float v  = fmaf(kM, tanha(mB * pre), kA);
                float tp = __shfl_xor_sync(0xffffffffu, v, 8);
                float q  = v * tp;
                float ig = __shfl_xor_sync(0xffffffffu, q, 4);
                float c  = fmaf(v, c1s[nt * 4 + ci], ig);
                c1s[nt * 4 + ci] = c;
                float h  = tp * tanha(c);
                if (mine) {
                    int u = uA + ((ci >= 2) ? 2 : 0);
                    int s = nt * 8 + 2 * tig + (ci & 1);
                    float hh = totf(h);
                    z1h[2 + u][s] = hh;
                    z2h[u][s]     = hh;
                }
            }
        }
        // stage x(t+1); prefetch x(t+2)
        if (w == 7) {
            z1h[0][lane] = totf(xv.x);
            z1h[1][lane] = totf(xv.y);
            if (t + 2 < Tt) xv = ((const float2*)x)[(size_t)(sBase + lane) * Tt + t + 2];
        }
        __syncthreads();   // h1(t), x(t+1) visible

        // ======== phase B: L2 gates (reads z2 h1 rows + h2(t-1) buffer) ========
        #pragma unroll
        for (int nt = 0; nt < 4; nt++) {
            accH[nt][0] = b2lo; accH[nt][1] = b2lo; accH[nt][2] = b2hi; accH[nt][3] = b2hi;
            accL[nt][0] = 0.f;  accL[nt][1] = 0.f;  accL[nt][2] = 0.f;  accL[nt][3] = 0.f;
        }
        #pragma unroll
        for (int kt = 0; kt < 8; kt++) {
            int k0 = kt * 8 + tig;
            int r0 = (kt < 4) ? k0 : (rb + k0 - 32);
            int r1 = r0 + 4;
            #pragma unroll
            for (int nt = 0; nt < 4; nt++) {
                int n = nt * 8 + gid;
                u32 bh0 = __float_as_uint(z2h[r0][n]), bh1 = __float_as_uint(z2h[r1][n]);
                mma8(accH[nt], a2h[kt], bh0, bh1);
                mma8(accL[nt], a2l[kt], bh0, bh1);
            }
        }

        // ======== L2 epilogue: h2(t) -> write buffer (no reader this step) ========
        #pragma unroll
        for (int nt = 0; nt < 4; nt++) {
            #pragma unroll
            for (int ci = 0; ci < 4; ci++) {
                float pre = accH[nt][ci] + accL[nt][ci];
                float v  = fmaf(kM, tanha(mB * pre), kA);
                float tp = __shfl_xor_sync(0xffffffffu, v, 8);
                float q  = v * tp;
                float ig = __shfl_xor_sync(0xffffffffu, q, 4);
                float c  = fmaf(v, c2s[nt * 4 + ci], ig);
                c2s[nt * 4 + ci] = c;
                float h  = tp * tanha(c);
                if (mine) {
                    int u = uA + ((ci >= 2) ? 2 : 0);
                    int s = nt * 8 + 2 * tig + (ci & 1);
                    z2h[wb2 + u][s] = totf(h);
                }
            }
        }
        __syncthreads();   // h2(t) visible for next step's head + phase B
    }

    // ======== final head: t = Tt-1 ========
    {
        const int rb = 32 + 32 * ((Tt - 1) & 1);
        float haH[4] = { boLo, boLo, boHi, boHi };
        float haL[4] = { 0.f, 0.f, 0.f, 0.f };
        int nt = w & 3, n = nt * 8 + gid;
        #pragma unroll
        for (int kt = 0; kt < 4; kt++) {
            int k0 = kt * 8 + tig;
            u32 bh0 = __float_as_uint(z2h[rb + k0][n]);
            u32 bh1 = __float_as_uint(z2h[rb + k0 + 4][n]);
            mma8(haH, ahh[kt], bh0, bh1);
            mma8(haL, ahl[kt], bh0, bh1);
        }
        int s0 = nt * 8 + 2 * tig;
        size_t r0 = ((size_t)(sBase + s0) * Tt + (Tt - 1)) * FOUT;
        size_t r1 = ((size_t)(sBase + s0 + 1) * Tt + (Tt - 1)) * FOUT;
        if (oLo < FOUT) { out[r0 + oLo] = haH[0] + haL[0]; out[r1 + oLo] = haH[1] + haL[1]; }
        if (oHi < FOUT) { out[r0 + oHi] = haH[2] + haL[2]; out[r1 + oHi] = haH[3] + haL[3]; }
    }
}

extern "C" void kernel_launch(void* const* d_in, const int* in_sizes, int n_in,
                              void* d_out, int out_size) {
    const float* x    = (const float*)d_in[0];
    const float* Wih1 = (const float*)d_in[1];
    const float* Whh1 = (const float*)d_in[2];
    const float* bih1 = (const float*)d_in[3];
    const float* bhh1 = (const float*)d_in[4];
    const float* Wih2 = (const float*)d_in[5];
    const float* Whh2 = (const float*)d_in[6];
    const float* bih2 = (const float*)d_in[7];
    const float* bhh2 = (const float*)d_in[8];
    const float* Wout = (const float*)d_in[9];
    const float* bout = (const float*)d_in[10];
    float* out = (float*)d_out;

    lstm_mma_kernel<<<NBLK, 256>>>(
        x, Wih1, Whh1, bih1, bhh1, Wih2, Whh2, bih2, bhh2, Wout, bout, out);
}

// round 16
// speedup vs baseline: 2.5254x; 1.1145x over previous
#include <cuda_runtime.h>

typedef unsigned int u32;

#define Tt    512
#define FOUT  20
#define NBLK  128

__device__ __forceinline__ float tanha(float x) {
    float y; asm("tanh.approx.f32 %0,%1;" : "=f"(y) : "f"(x)); return y;
}
__device__ __forceinline__ float totf(float x) {
    u32 r; asm("cvt.rna.tf32.f32 %0,%1;" : "=r"(r) : "f"(x));
    return __uint_as_float(r);
}
__device__ __forceinline__ u32 tfu(float x) {
    u32 r; asm("cvt.rna.tf32.f32 %0,%1;" : "=r"(r) : "f"(x));
    return r;
}
// D = A(16x8 tf32, row) * B(8x8 tf32, col) + D   (f32 accum)
__device__ __forceinline__ void mma8(float c[4], const u32 a[4], u32 b0, u32 b1) {
    asm volatile(
        "mma.sync.aligned.m16n8k8.row.col.f32.tf32.tf32.f32 "
        "{%0,%1,%2,%3},{%4,%5,%6,%7},{%8,%9},{%0,%1,%2,%3};"
        : "+f"(c[0]), "+f"(c[1]), "+f"(c[2]), "+f"(c[3])
        : "r"(a[0]), "r"(a[1]), "r"(a[2]), "r"(a[3]), "r"(b0), "r"(b1));
}

#define ZSTR 40   // stride 40: bank = (8*tig + gid + c) % 32 -> conflict-free B loads

__global__ void __launch_bounds__(256, 1)
lstm_mma_kernel(const float* __restrict__ x,
                const float* __restrict__ Wih1, const float* __restrict__ Whh1,
                const float* __restrict__ bih1, const float* __restrict__ bhh1,
                const float* __restrict__ Wih2, const float* __restrict__ Whh2,
                const float* __restrict__ bih2, const float* __restrict__ bhh2,
                const float* __restrict__ Wout, const float* __restrict__ bout,
                float* __restrict__ out)
{
    // z tiles (tf32-hi only), stride ZSTR.
    // z1: rows 0..1 = x(t), 2..33 = h1, 34..39 pad.
    // z2: rows 0..31 = h1(t); h2 double-buffered: rows 32..63 (par 0), 64..95 (par 1).
    __shared__ float z1h[40][ZSTR];
    __shared__ float z2h[96][ZSTR];

    const int tid  = threadIdx.x;
    const int w    = tid >> 5, lane = tid & 31;
    const int gid  = lane >> 2, tig = lane & 3;
    const int sBase = blockIdx.x * 32;

    for (int i = tid; i < 40 * ZSTR; i += 256) (&z1h[0][0])[i] = 0.f;
    for (int i = tid; i < 96 * ZSTR; i += 256) (&z2h[0][0])[i] = 0.f;

    // ---- gate-row indices: global row R = w*16 + gid (+8); R = 4*unit + gate ----
    const int Rlo = w * 16 + gid, Rhi = Rlo + 8;

    auto w1v = [&](int R, int k) -> float {
        if (k >= 34) return 0.f;
        int u = R >> 2, g = R & 3;
        return (k < 2) ? Wih1[(g * 32 + u) * 2 + k] : Whh1[(g * 32 + u) * 32 + (k - 2)];
    };
    auto w2v = [&](int R, int k) -> float {
        int u = R >> 2, g = R & 3;
        return (k < 32) ? Wih2[(g * 32 + u) * 32 + k] : Whh2[(g * 32 + u) * 32 + (k - 32)];
    };

    // ---- A fragments (weights resident in registers; hi + lo split) ----
    u32 a1h[5][4], a1l[5][4];
    #pragma unroll
    for (int kt = 0; kt < 5; kt++) {
        int rows[2] = { Rlo, Rhi };
        #pragma unroll
        for (int i = 0; i < 4; i++) {
            int r = rows[i & 1];
            int k = kt * 8 + tig + ((i >= 2) ? 4 : 0);
            float v = w1v(r, k), hi = totf(v);
            a1h[kt][i] = __float_as_uint(hi);
            a1l[kt][i] = tfu(v - hi);
        }
    }
    u32 a2h[8][4], a2l[8][4];
    #pragma unroll
    for (int kt = 0; kt < 8; kt++) {
        int rows[2] = { Rlo, Rhi };
        #pragma unroll
        for (int i = 0; i < 4; i++) {
            int r = rows[i & 1];
            int k = kt * 8 + tig + ((i >= 2) ? 4 : 0);
            float v = w2v(r, k), hi = totf(v);
            a2h[kt][i] = __float_as_uint(hi);
            a2l[kt][i] = tfu(v - hi);
        }
    }
    // head A: warp w -> (mt = w>>2, nt = w&3); rows = mt*16 + gid (+8), K=32
    const int oLo = (w >> 2) * 16 + gid, oHi = oLo + 8;
    u32 ahh[4][4], ahl[4][4];
    #pragma unroll
    for (int kt = 0; kt < 4; kt++) {
        int rows[2] = { oLo, oHi };
        #pragma unroll
        for (int i = 0; i < 4; i++) {
            int r = rows[i & 1];
            int k = kt * 8 + tig + ((i >= 2) ? 4 : 0);
            float v = (r < FOUT) ? Wout[r * 32 + k] : 0.f;
            float hi = totf(v);
            ahh[kt][i] = __float_as_uint(hi);
            ahl[kt][i] = tfu(v - hi);
        }
    }

    // ---- biases / activation constants ----
    const int uL = Rlo >> 2, gL = Rlo & 3;
    const int uH = Rhi >> 2;
    const float b1lo = bih1[gL * 32 + uL] + bhh1[gL * 32 + uL];
    const float b1hi = bih1[gL * 32 + uH] + bhh1[gL * 32 + uH];
    const float b2lo = bih2[gL * 32 + uL] + bhh2[gL * 32 + uL];
    const float b2hi = bih2[gL * 32 + uH] + bhh2[gL * 32 + uH];
    const float boLo = (oLo < FOUT) ? bout[oLo] : 0.f;
    const float boHi = (oHi < FOUT) ? bout[oHi] : 0.f;
    const float mB = (gL == 2) ? 1.f : 0.5f;
    const float kM = (gL == 2) ? 1.f : 0.5f;
    const float kA = (gL == 2) ? 0.f : 0.5f;
    const bool  mine = (gL == 1);
    const int   uA   = 4 * w + (gid >> 2);

    // stage x(0); prefetch x(1)
    float2 xv = make_float2(0.f, 0.f);
    if (w == 7) {
        float2 x0 = ((const float2*)x)[(size_t)(sBase + lane) * Tt];
        z1h[0][lane] = totf(x0.x);
        z1h[1][lane] = totf(x0.y);
        xv = ((const float2*)x)[(size_t)(sBase + lane) * Tt + 1];
    }
    __syncthreads();

    float c1s[16], c2s[16];
    #pragma unroll
    for (int i = 0; i < 16; i++) { c1s[i] = 0.f; c2s[i] = 0.f; }

    float accH[4][4], accL[4][4];

    #pragma unroll 1
    for (int t = 0; t < Tt; t++) {
        const int rb = 32 + 32 * ((t & 1) ^ 1);   // h2(t-1) buffer base
        const int wb2 = 32 + 32 * (t & 1);        // h2(t) buffer base

        // ======== head for t-1 (first: overlaps phase A) ========
        float haH[4], haL[4];
        if (t > 0) {
            haH[0] = boLo; haH[1] = boLo; haH[2] = boHi; haH[3] = boHi;
            haL[0] = 0.f;  haL[1] = 0.f;  haL[2] = 0.f;  haL[3] = 0.f;
            int nt = w & 3, n = nt * 8 + gid;
            #pragma unroll
            for (int kt = 0; kt < 4; kt++) {
                int k0 = kt * 8 + tig;
                u32 bh0 = __float_as_uint(z2h[rb + k0][n]);
                u32 bh1 = __float_as_uint(z2h[rb + k0 + 4][n]);
                mma8(haH, ahh[kt], bh0, bh1);
                mma8(haL, ahl[kt], bh0, bh1);
            }
        }

        // ======== phase A: L1 gates (reads z1) ========
        #pragma unroll
        for (int nt = 0; nt < 4; nt++) {
            accH[nt][0] = b1lo; accH[nt][1] = b1lo; accH[nt][2] = b1hi; accH[nt][3] = b1hi;
            accL[nt][0] = 0.f;  accL[nt][1] = 0.f;  accL[nt][2] = 0.f;  accL[nt][3] = 0.f;
        }
        #pragma unroll
        for (int kt = 0; kt < 5; kt++) {
            int k0 = kt * 8 + tig;
            #pragma unroll
            for (int nt = 0; nt < 4; nt++) {
                int n = nt * 8 + gid;
                u32 bh0 = __float_as_uint(z1h[k0][n]), bh1 = __float_as_uint(z1h[k0 + 4][n]);
                mma8(accH[nt], a1h[kt], bh0, bh1);
                mma8(accL[nt], a1l[kt], bh0, bh1);
            }
        }

        // head stores (mma results drained by now)
        if (t > 0) {
            int nt = w & 3;
            int s0 = nt * 8 + 2 * tig;
            size_t r0 = ((size_t)(sBase + s0) * Tt + (t - 1)) * FOUT;
            size_t r1 = ((size_t)(sBase + s0 + 1) * Tt + (t - 1)) * FOUT;
            if (oLo < FOUT) { out[r0 + oLo] = haH[0] + haL[0]; out[r1 + oLo] = haH[1] + haL[1]; }
            if (oHi < FOUT) { out[r0 + oHi] = haH[2] + haL[2]; out[r1 + oHi] = haH[3] + haL[3]; }
        }
        __syncthreads();   // phase A z1 reads + head/phase-B-prev z2 reads complete

        // ======== L1 epilogue: h1(t) -> z1 rows 2.., z2 rows 0..31 ========
        #pragma unroll
        for (int nt = 0; nt < 4; nt++) {
            #pragma unroll
            for (int ci = 0; ci < 4; ci++) {
                float pre = accH[nt][ci] + accL[nt][ci];
                float v  = fmaf(kM, tanha(mB * pre), kA);
                float tp = __shfl_xor_sync(0xffffffffu, v, 8);
                float q  = v * tp;
                float ig = __shfl_xor_sync(0xffffffffu, q, 4);
                float c  = fmaf(v, c1s[nt * 4 + ci], ig);
                c1s[nt * 4 + ci] = c;
                float h  = tp * tanha(c);
                if (mine) {
                    int u = uA + ((ci >= 2) ? 2 : 0);
                    int s = nt * 8 + 2 * tig + (ci & 1);
                    float hh = totf(h);
                    z1h[2 + u][s] = hh;
                    z2h[u][s]     = hh;
                }
            }
        }
        // stage x(t+1); prefetch x(t+2)
        if (w == 7) {
            z1h[0][lane] = totf(xv.x);
            z1h[1][lane] = totf(xv.y);
            if (t + 2 < Tt) xv = ((const float2*)x)[(size_t)(sBase + lane) * Tt + t + 2];
        }
        __syncthreads();   // h1(t), x(t+1) visible

        // ======== phase B: L2 gates (reads z2 h1 rows + h2(t-1) buffer) ========
        #pragma unroll
        for (int nt = 0; nt < 4; nt++) {
            accH[nt][0] = b2lo; accH[nt][1] = b2lo; accH[nt][2] = b2hi; accH[nt][3] = b2hi;
            accL[nt][0] = 0.f;  accL[nt][1] = 0.f;  accL[nt][2] = 0.f;  accL[nt][3] = 0.f;
        }
        #pragma unroll
        for (int kt = 0; kt < 8; kt++) {
            int k0 = kt * 8 + tig;
            int r0 = (kt < 4) ? k0 : (rb + k0 - 32);
            int r1 = r0 + 4;
            #pragma unroll
            for (int nt = 0; nt < 4; nt++) {
                int n = nt * 8 + gid;
                u32 bh0 = __float_as_uint(z2h[r0][n]), bh1 = __float_as_uint(z2h[r1][n]);
                mma8(accH[nt], a2h[kt], bh0, bh1);
                mma8(accL[nt], a2l[kt], bh0, bh1);
            }
        }

        // ======== L2 epilogue: h2(t) -> write buffer (no reader this step) ========
        #pragma unroll
        for (int nt = 0; nt < 4; nt++) {
            #pragma unroll
            for (int ci = 0; ci < 4; ci++) {
                float pre = accH[nt][ci] + accL[nt][ci];
                float v  = fmaf(kM, tanha(mB * pre), kA);
                float tp = __shfl_xor_sync(0xffffffffu, v, 8);
                float q  = v * tp;
                float ig = __shfl_xor_sync(0xffffffffu, q, 4);
                float c  = fmaf(v, c2s[nt * 4 + ci], ig);
                c2s[nt * 4 + ci] = c;
                float h  = tp * tanha(c);
                if (mine) {
                    int u = uA + ((ci >= 2) ? 2 : 0);
                    int s = nt * 8 + 2 * tig + (ci & 1);
                    z2h[wb2 + u][s] = totf(h);
                }
            }
        }
        __syncthreads();   // h2(t) visible for next step's head + phase B
    }

    // ======== final head: t = Tt-1 ========
    {
        const int rb = 32 + 32 * ((Tt - 1) & 1);
        float haH[4] = { boLo, boLo, boHi, boHi };
        float haL[4] = { 0.f, 0.f, 0.f, 0.f };
        int nt = w & 3, n = nt * 8 + gid;
        #pragma unroll
        for (int kt = 0; kt < 4; kt++) {
            int k0 = kt * 8 + tig;
            u32 bh0 = __float_as_uint(z2h[rb + k0][n]);
            u32 bh1 = __float_as_uint(z2h[rb + k0 + 4][n]);
            mma8(haH, ahh[kt], bh0, bh1);
            mma8(haL, ahl[kt], bh0, bh1);
        }
        int s0 = nt * 8 + 2 * tig;
        size_t r0 = ((size_t)(sBase + s0) * Tt + (Tt - 1)) * FOUT;
        size_t r1 = ((size_t)(sBase + s0 + 1) * Tt + (Tt - 1)) * FOUT;
        if (oLo < FOUT) { out[r0 + oLo] = haH[0] + haL[0]; out[r1 + oLo] = haH[1] + haL[1]; }
        if (oHi < FOUT) { out[r0 + oHi] = haH[2] + haL[2]; out[r1 + oHi] = haH[3] + haL[3]; }
    }
}

extern "C" void kernel_launch(void* const* d_in, const int* in_sizes, int n_in,
                              void* d_out, int out_size) {
    const float* x    = (const float*)d_in[0];
    const float* Wih1 = (const float*)d_in[1];
    const float* Whh1 = (const float*)d_in[2];
    const float* bih1 = (const float*)d_in[3];
    const float* bhh1 = (const float*)d_in[4];
    const float* Wih2 = (const float*)d_in[5];
    const float* Whh2 = (const float*)d_in[6];
    const float* bih2 = (const float*)d_in[7];
    const float* bhh2 = (const float*)d_in[8];
    const float* Wout = (const float*)d_in[9];
    const float* bout = (const float*)d_in[10];
    float* out = (float*)d_out;

    lstm_mma_kernel<<<NBLK, 256>>>(
        x, Wih1, Whh1, bih1, bhh1, Wih2, Whh2, bih2, bhh2, Wout, bout, out);
}

// round 17
// speedup vs baseline: 3.2485x; 1.2864x over previous
#include <cuda_runtime.h>

typedef unsigned int u32;

#define Tt    512
#define FOUT  20
#define NBLK  128

__device__ __forceinline__ float tanha(float x) {
    float y; asm("tanh.approx.f32 %0,%1;" : "=f"(y) : "f"(x)); return y;
}
__device__ __forceinline__ float totf(float x) {
    u32 r; asm("cvt.rna.tf32.f32 %0,%1;" : "=r"(r) : "f"(x));
    return __uint_as_float(r);
}
__device__ __forceinline__ u32 tfu(float x) {
    u32 r; asm("cvt.rna.tf32.f32 %0,%1;" : "=r"(r) : "f"(x));
    return r;
}
// D = A(16x8 tf32, row) * B(8x8 tf32, col) + D   (f32 accum)
__device__ __forceinline__ void mma8(float c[4], const u32 a[4], u32 b0, u32 b1) {
    asm volatile(
        "mma.sync.aligned.m16n8k8.row.col.f32.tf32.tf32.f32 "
        "{%0,%1,%2,%3},{%4,%5,%6,%7},{%8,%9},{%0,%1,%2,%3};"
        : "+f"(c[0]), "+f"(c[1]), "+f"(c[2]), "+f"(c[3])
        : "r"(a[0]), "r"(a[1]), "r"(a[2]), "r"(a[3]), "r"(b0), "r"(b1));
}

#define ZSTR 40   // bank = (8*tig + gid + c) % 32 -> conflict-free B loads

__global__ void __launch_bounds__(256, 1)
lstm_mma_kernel(const float* __restrict__ x,
                const float* __restrict__ Wih1, const float* __restrict__ Whh1,
                const float* __restrict__ bih1, const float* __restrict__ bhh1,
                const float* __restrict__ Wih2, const float* __restrict__ Whh2,
                const float* __restrict__ bih2, const float* __restrict__ bhh2,
                const float* __restrict__ Wout, const float* __restrict__ bout,
                float* __restrict__ out)
{
    // z tiles (tf32), stride ZSTR.
    // z1: rows 0..1 = x(t), 2..33 = h1, 34..39 pad.
    // z2: rows 0..31 = h1(t); h2 double-buffered: rows 32..63 (par 0), 64..95 (par 1).
    __shared__ float z1h[40][ZSTR];
    __shared__ float z2h[96][ZSTR];

    const int tid  = threadIdx.x;
    const int w    = tid >> 5, lane = tid & 31;
    const int gid  = lane >> 2, tig = lane & 3;
    const int sBase = blockIdx.x * 32;

    for (int i = tid; i < 40 * ZSTR; i += 256) (&z1h[0][0])[i] = 0.f;
    for (int i = tid; i < 96 * ZSTR; i += 256) (&z2h[0][0])[i] = 0.f;

    // ---- gate-row indices: global row R = w*16 + gid (+8); R = 4*unit + gate ----
    const int Rlo = w * 16 + gid, Rhi = Rlo + 8;

    auto w1v = [&](int R, int k) -> float {
        if (k >= 34) return 0.f;
        int u = R >> 2, g = R & 3;
        return (k < 2) ? Wih1[(g * 32 + u) * 2 + k] : Whh1[(g * 32 + u) * 32 + (k - 2)];
    };
    auto w2v = [&](int R, int k) -> float {
        int u = R >> 2, g = R & 3;
        return (k < 32) ? Wih2[(g * 32 + u) * 32 + k] : Whh2[(g * 32 + u) * 32 + (k - 32)];
    };

    // ---- A fragments (weights resident in registers; pure tf32) ----
    u32 a1h[5][4];
    #pragma unroll
    for (int kt = 0; kt < 5; kt++) {
        int rows[2] = { Rlo, Rhi };
        #pragma unroll
        for (int i = 0; i < 4; i++) {
            int r = rows[i & 1];
            int k = kt * 8 + tig + ((i >= 2) ? 4 : 0);
            a1h[kt][i] = tfu(w1v(r, k));
        }
    }
    u32 a2h[8][4];
    #pragma unroll
    for (int kt = 0; kt < 8; kt++) {
        int rows[2] = { Rlo, Rhi };
        #pragma unroll
        for (int i = 0; i < 4; i++) {
            int r = rows[i & 1];
            int k = kt * 8 + tig + ((i >= 2) ? 4 : 0);
            a2h[kt][i] = tfu(w2v(r, k));
        }
    }
    // head A: warp w -> (mt = w>>2, nt = w&3); rows = mt*16 + gid (+8), K=32
    const int oLo = (w >> 2) * 16 + gid, oHi = oLo + 8;
    u32 ahh[4][4];
    #pragma unroll
    for (int kt = 0; kt < 4; kt++) {
        int rows[2] = { oLo, oHi };
        #pragma unroll
        for (int i = 0; i < 4; i++) {
            int r = rows[i & 1];
            int k = kt * 8 + tig + ((i >= 2) ? 4 : 0);
            ahh[kt][i] = tfu((r < FOUT) ? Wout[r * 32 + k] : 0.f);
        }
    }

    // ---- biases / activation constants ----
    const int uL = Rlo >> 2, gL = Rlo & 3;
    const int uH = Rhi >> 2;
    const float b1lo = bih1[gL * 32 + uL] + bhh1[gL * 32 + uL];
    const float b1hi = bih1[gL * 32 + uH] + bhh1[gL * 32 + uH];
    const float b2lo = bih2[gL * 32 + uL] + bhh2[gL * 32 + uL];
    const float b2hi = bih2[gL * 32 + uH] + bhh2[gL * 32 + uH];
    const float boLo = (oLo < FOUT) ? bout[oLo] : 0.f;
    const float boHi = (oHi < FOUT) ? bout[oHi] : 0.f;
    const float mB = (gL == 2) ? 1.f : 0.5f;
    const float kM = (gL == 2) ? 1.f : 0.5f;
    const float kA = (gL == 2) ? 0.f : 0.5f;
    const bool  mine = (gL == 1);
    const int   uA   = 4 * w + (gid >> 2);

    // stage x(0); prefetch x(1)
    float2 xv = make_float2(0.f, 0.f);
    if (w == 7) {
        float2 x0 = ((const float2*)x)[(size_t)(sBase + lane) * Tt];
        z1h[0][lane] = totf(x0.x);
        z1h[1][lane] = totf(x0.y);
        xv = ((const float2*)x)[(size_t)(sBase + lane) * Tt + 1];
    }
    __syncthreads();

    float c1s[16], c2s[16];
    #pragma unroll
    for (int i = 0; i < 16; i++) { c1s[i] = 0.f; c2s[i] = 0.f; }

    float accH[4][4];

    #pragma unroll 1
    for (int t = 0; t < Tt; t++) {
        const int rb = 32 + 32 * ((t & 1) ^ 1);   // h2(t-1) buffer base
        const int wb2 = 32 + 32 * (t & 1);        // h2(t) buffer base

        // ======== head for t-1 (first: overlaps phase A) ========
        float haH[4];
        if (t > 0) {
            haH[0] = boLo; haH[1] = boLo; haH[2] = boHi; haH[3] = boHi;
            int nt = w & 3, n = nt * 8 + gid;
            #pragma unroll
            for (int kt = 0; kt < 4; kt++) {
                int k0 = kt * 8 + tig;
                u32 bh0 = __float_as_uint(z2h[rb + k0][n]);
                u32 bh1 = __float_as_uint(z2h[rb + k0 + 4][n]);
                mma8(haH, ahh[kt], bh0, bh1);
            }
        }

        // ======== phase A: L1 gates (reads z1) ========
        #pragma unroll
        for (int nt = 0; nt < 4; nt++) {
            accH[nt][0] = b1lo; accH[nt][1] = b1lo; accH[nt][2] = b1hi; accH[nt][3] = b1hi;
        }
        #pragma unroll
        for (int kt = 0; kt < 5; kt++) {
            int k0 = kt * 8 + tig;
            #pragma unroll
            for (int nt = 0; nt < 4; nt++) {
                int n = nt * 8 + gid;
                u32 bh0 = __float_as_uint(z1h[k0][n]), bh1 = __float_as_uint(z1h[k0 + 4][n]);
                mma8(accH[nt], a1h[kt], bh0, bh1);
            }
        }

        // head stores (mma results drained by now)
        if (t > 0) {
            int nt = w & 3;
            int s0 = nt * 8 + 2 * tig;
            size_t r0 = ((size_t)(sBase + s0) * Tt + (t - 1)) * FOUT;
            size_t r1 = ((size_t)(sBase + s0 + 1) * Tt + (t - 1)) * FOUT;
            if (oLo < FOUT) { out[r0 + oLo] = haH[0]; out[r1 + oLo] = haH[1]; }
            if (oHi < FOUT) { out[r0 + oHi] = haH[2]; out[r1 + oHi] = haH[3]; }
        }
        __syncthreads();   // phase A z1 reads + head/phase-B-prev z2 reads complete

        // ======== L1 epilogue: h1(t) -> z1 rows 2.., z2 rows 0..31 ========
        #pragma unroll
        for (int nt = 0; nt < 4; nt++) {
            #pragma unroll
            for (int ci = 0; ci < 4; ci++) {
                float v  = fmaf(kM, tanha(mB * accH[nt][ci]), kA);
                float tp = __shfl_xor_sync(0xffffffffu, v, 8);
                float q  = v * tp;
                float ig = __shfl_xor_sync(0xffffffffu, q, 4);
                float c  = fmaf(v, c1s[nt * 4 + ci], ig);
                c1s[nt * 4 + ci] = c;
                float h  = tp * tanha(c);
                if (mine) {
                    int u = uA + ((ci >= 2) ? 2 : 0);
                    int s = nt * 8 + 2 * tig + (ci & 1);
                    float hh = totf(h);
                    z1h[2 + u][s] = hh;
                    z2h[u][s]     = hh;
                }
            }
        }
        // stage x(t+1); prefetch x(t+2)
        if (w == 7) {
            z1h[0][lane] = totf(xv.x);
            z1h[1][lane] = totf(xv.y);
            if (t + 2 < Tt) xv = ((const float2*)x)[(size_t)(sBase + lane) * Tt + t + 2];
        }
        __syncthreads();   // h1(t), x(t+1) visible

        // ======== phase B: L2 gates (reads z2 h1 rows + h2(t-1) buffer) ========
        #pragma unroll
        for (int nt = 0; nt < 4; nt++) {
            accH[nt][0] = b2lo; accH[nt][1] = b2lo; accH[nt][2] = b2hi; accH[nt][3] = b2hi;
        }
        #pragma unroll
        for (int kt = 0; kt < 8; kt++) {
            int k0 = kt * 8 + tig;
            int r0 = (kt < 4) ? k0 : (rb + k0 - 32);
            int r1 = r0 + 4;
            #pragma unroll
            for (int nt = 0; nt < 4; nt++) {
                int n = nt * 8 + gid;
                u32 bh0 = __float_as_uint(z2h[r0][n]), bh1 = __float_as_uint(z2h[r1][n]);
                mma8(accH[nt], a2h[kt], bh0, bh1);
            }
        }

        // ======== L2 epilogue: h2(t) -> write buffer (no reader this step) ========
        #pragma unroll
        for (int nt = 0; nt < 4; nt++) {
            #pragma unroll
            for (int ci = 0; ci < 4; ci++) {
                float v  = fmaf(kM, tanha(mB * accH[nt][ci]), kA);
                float tp = __shfl_xor_sync(0xffffffffu, v, 8);
                float q  = v * tp;
                float ig = __shfl_xor_sync(0xffffffffu, q, 4);
                float c  = fmaf(v, c2s[nt * 4 + ci], ig);
                c2s[nt * 4 + ci] = c;
                float h  = tp * tanha(c);
                if (mine) {
                    int u = uA + ((ci >= 2) ? 2 : 0);
                    int s = nt * 8 + 2 * tig + (ci & 1);
                    z2h[wb2 + u][s] = totf(h);
                }
            }
        }
        __syncthreads();   // h2(t) visible for next step's head + phase B
    }

    // ======== final head: t = Tt-1 ========
    {
        const int rb = 32 + 32 * ((Tt - 1) & 1);
        float haH[4] = { boLo, boLo, boHi, boHi };
        int nt = w & 3, n = nt * 8 + gid;
        #pragma unroll
        for (int kt = 0; kt < 4; kt++) {
            int k0 = kt * 8 + tig;
            u32 bh0 = __float_as_uint(z2h[rb + k0][n]);
            u32 bh1 = __float_as_uint(z2h[rb + k0 + 4][n]);
            mma8(haH, ahh[kt], bh0, bh1);
        }
        int s0 = nt * 8 + 2 * tig;
        size_t r0 = ((size_t)(sBase + s0) * Tt + (Tt - 1)) * FOUT;
        size_t r1 = ((size_t)(sBase + s0 + 1) * Tt + (Tt - 1)) * FOUT;
        if (oLo < FOUT) { out[r0 + oLo] = haH[0]; out[r1 + oLo] = haH[1]; }
        if (oHi < FOUT) { out[r0 + oHi] = haH[2]; out[r1 + oHi] = haH[3]; }
    }
}

extern "C" void kernel_launch(void* const* d_in, const int* in_sizes, int n_in,
                              void* d_out, int out_size) {
    const float* x    = (const float*)d_in[0];
    const float* Wih1 = (const float*)d_in[1];
    const float* Whh1 = (const float*)d_in[2];
    const float* bih1 = (const float*)d_in[3];
    const float* bhh1 = (const float*)d_in[4];
    const float* Wih2 = (const float*)d_in[5];
    const float* Whh2 = (const float*)d_in[6];
    const float* bih2 = (const float*)d_in[7];
    const float* bhh2 = (const float*)d_in[8];
    const float* Wout = (const float*)d_in[9];
    const float* bout = (const float*)d_in[10];
    float* out = (float*)d_out;

    lstm_mma_kernel<<<NBLK, 256>>>(
        x, Wih1, Whh1, bih1, bhh1, Wih2, Whh2, bih2, bhh2, Wout, bout, out);
}